// round 6
// baseline (speedup 1.0000x reference)
#include <cuda_runtime.h>
#include <cstdint>

// DurationCalculator: B=256, Y=4096, X=1024
//   weights_argmax[b,y] = duration[b,y] + (y < output_length[b] ? 0 : -10000)
//   durations[b,x]      = #{ y < output_length[b] : duration[b,y] == x }
// duration values are in [0, X): all valid elements in range, all masked
// elements drop below 0 (reference clips them into the discarded bucket).
// Output dtype float32. Layout: [B*Y weights_argmax][B*X durations].
//
// Single kernel, 512 CTAs = 2 per row (halves the worst-case serialized smem
// ATOMS chain and fixes SM pairing imbalance). Merge is fused via a
// last-arrival protocol: both CTAs flush partials to global scratch, fence,
// bump a per-row flag; the second arriver sums peer partial (L2) with its own
// smem histogram and writes the final floats. Flag uses parity, so it needs
// no reset across graph replays (each replay adds exactly 2 per row).

#define B_DIM 256
#define Y_DIM 4096
#define X_DIM 1024
#define MASK_PENALTY (-10000)

__device__ int g_partial[2 * B_DIM * X_DIM];   // 2 MiB partial histograms
__device__ unsigned int g_flag[B_DIM];         // zero-init; monotonic counter

__global__ __launch_bounds__(512, 4)
void duration_calc_kernel(const int* __restrict__ duration,
                          const int* __restrict__ output_length,
                          float* __restrict__ weights_out,
                          float* __restrict__ hist_out)
{
    __shared__ int hist[X_DIM];
    __shared__ unsigned int s_old;

    const int bid  = blockIdx.x;            // 0..511
    const int row  = bid >> 1;              // 0..255
    const int half = bid & 1;
    const int tid  = threadIdx.x;           // 0..511

    hist[tid]       = 0;
    hist[tid + 512] = 0;
    __syncthreads();

    const int len = __ldg(&output_length[row]);

    // Half-row = 2048 ints = 512 int4; one int4 per thread.
    const int gid4 = row * (Y_DIM / 4) + half * 512 + tid;
    const int y0   = (half * 512 + tid) * 4;

    const int4 v = reinterpret_cast<const int4*>(duration)[gid4];

    const bool m0 = (y0 + 0) < len;
    const bool m1 = (y0 + 1) < len;
    const bool m2 = (y0 + 2) < len;
    const bool m3 = (y0 + 3) < len;

    float4 w;
    w.x = (float)(v.x + (m0 ? 0 : MASK_PENALTY));
    w.y = (float)(v.y + (m1 ? 0 : MASK_PENALTY));
    w.z = (float)(v.z + (m2 ? 0 : MASK_PENALTY));
    w.w = (float)(v.w + (m3 ? 0 : MASK_PENALTY));

    reinterpret_cast<float4*>(weights_out)[gid4] = w;

    if (m0) atomicAdd(&hist[v.x], 1);
    if (m1) atomicAdd(&hist[v.y], 1);
    if (m2) atomicAdd(&hist[v.z], 1);
    if (m3) atomicAdd(&hist[v.w], 1);

    __syncthreads();

    // Flush partial histogram (coalesced, non-atomic).
    int* part = g_partial + (size_t)bid * X_DIM;
    part[tid]       = hist[tid];
    part[tid + 512] = hist[tid + 512];

    // Release partial, then bump the per-row arrival counter.
    __threadfence();
    if (tid == 0) s_old = atomicAdd(&g_flag[row], 1u);
    __syncthreads();

    // Second arriver of this replay (odd old value) performs the merge.
    if (s_old & 1u) {
        __threadfence();   // acquire: order peer-partial reads after the flag
        const int* peer = g_partial + (size_t)(bid ^ 1) * X_DIM;
        float* out = hist_out + (size_t)row * X_DIM;
        out[tid]       = (float)(hist[tid]       + peer[tid]);
        out[tid + 512] = (float)(hist[tid + 512] + peer[tid + 512]);
    }
}

extern "C" void kernel_launch(void* const* d_in, const int* in_sizes, int n_in,
                              void* d_out, int out_size)
{
    const int* duration      = (const int*)d_in[0];   // (B, Y) int32
    const int* output_length = (const int*)d_in[1];   // (B,)   int32
    // d_in[2] (x_steps) is the compile-time constant X_DIM = 1024.

    float* weights_out = (float*)d_out;                         // B*Y floats
    float* hist_out    = (float*)d_out + (size_t)B_DIM * Y_DIM; // B*X floats

    duration_calc_kernel<<<2 * B_DIM, 512>>>(duration, output_length,
                                             weights_out, hist_out);
}

// round 7
// speedup vs baseline: 1.0295x; 1.0295x over previous
#include <cuda_runtime.h>
#include <cstdint>

// DurationCalculator: B=256, Y=4096, X=1024
//   weights_argmax[b,y] = duration[b,y] + (y < output_length[b] ? 0 : -10000)
//   durations[b,x]      = #{ y < output_length[b] : duration[b,y] == x }
// duration values lie in [0, X): all valid elements are in range; masked ones
// drop below 0 (reference clips them into the discarded bucket).
// Output dtype float32. Layout: [B*Y weights_argmax][B*X durations].
//
// 1024 CTAs = 4 per row (quarter-row) for near-perfect ATOMS balance.
// Merge fused via release/acquire atomic arrival counter: 4th arriver sums
// the 3 peer partials (L2) with its own smem histogram. No fences, no extra
// kernel, no cluster barriers. Counter parity is stable across graph replays
// (each replay adds exactly 4 per row).

#define B_DIM 256
#define Y_DIM 4096
#define X_DIM 1024
#define MASK_PENALTY (-10000)

__device__ int g_partial[4 * B_DIM * X_DIM];   // 4 MiB partial histograms
__device__ unsigned int g_flag[B_DIM];         // zero-init; monotonic counter

__global__ __launch_bounds__(256, 8)
void duration_calc_kernel(const int* __restrict__ duration,
                          const int* __restrict__ output_length,
                          float* __restrict__ weights_out,
                          float* __restrict__ hist_out)
{
    __shared__ int hist[X_DIM];
    __shared__ unsigned int s_old;

    const int bid = blockIdx.x;          // 0..1023
    const int row = bid >> 2;            // 0..255
    const int q   = bid & 3;             // quarter index
    const int tid = threadIdx.x;         // 0..255

    hist[tid]       = 0;
    hist[tid + 256] = 0;
    hist[tid + 512] = 0;
    hist[tid + 768] = 0;
    __syncthreads();

    const int len = __ldg(&output_length[row]);

    // Quarter-row = 1024 ints = 256 int4; one int4 per thread.
    const int idx4 = row * (Y_DIM / 4) + q * 256 + tid;
    const int y0   = (q * 256 + tid) * 4;

    const int4 v = reinterpret_cast<const int4*>(duration)[idx4];

    const bool m0 = (y0 + 0) < len;
    const bool m1 = (y0 + 1) < len;
    const bool m2 = (y0 + 2) < len;
    const bool m3 = (y0 + 3) < len;

    float4 w;
    w.x = (float)(v.x + (m0 ? 0 : MASK_PENALTY));
    w.y = (float)(v.y + (m1 ? 0 : MASK_PENALTY));
    w.z = (float)(v.z + (m2 ? 0 : MASK_PENALTY));
    w.w = (float)(v.w + (m3 ? 0 : MASK_PENALTY));

    reinterpret_cast<float4*>(weights_out)[idx4] = w;

    if (m0) atomicAdd(&hist[v.x], 1);
    if (m1) atomicAdd(&hist[v.y], 1);
    if (m2) atomicAdd(&hist[v.z], 1);
    if (m3) atomicAdd(&hist[v.w], 1);

    __syncthreads();

    // Flush partial histogram, coalesced int4 (bins 4t..4t+3 per thread).
    int* part = g_partial + (size_t)bid * X_DIM;
    reinterpret_cast<int4*>(part)[tid] =
        *reinterpret_cast<const int4*>(&hist[4 * tid]);

    // One release+acquire atomic per CTA. bar.sync orders all threads' prior
    // stores before thread 0's release; the acquire orders our peer-partial
    // reads after the peers' releases (PTX memory model, transitive).
    if (tid == 0) {
        unsigned int old;
        asm volatile("atom.acq_rel.gpu.global.add.u32 %0, [%1], %2;"
                     : "=r"(old) : "l"(&g_flag[row]), "r"(1u) : "memory");
        s_old = old;
    }
    __syncthreads();

    // Fourth arriver of this replay merges (each replay adds exactly 4).
    if ((s_old & 3u) == 3u) {
        const int* p0 = g_partial + (size_t)((row << 2) | ((q + 1) & 3)) * X_DIM;
        const int* p1 = g_partial + (size_t)((row << 2) | ((q + 2) & 3)) * X_DIM;
        const int* p2 = g_partial + (size_t)((row << 2) | ((q + 3) & 3)) * X_DIM;

        const int4 a = *reinterpret_cast<const int4*>(&hist[4 * tid]);
        const int4 b = reinterpret_cast<const int4*>(p0)[tid];
        const int4 c = reinterpret_cast<const int4*>(p1)[tid];
        const int4 d = reinterpret_cast<const int4*>(p2)[tid];

        float4 o;
        o.x = (float)(a.x + b.x + c.x + d.x);
        o.y = (float)(a.y + b.y + c.y + d.y);
        o.z = (float)(a.z + b.z + c.z + d.z);
        o.w = (float)(a.w + b.w + c.w + d.w);

        reinterpret_cast<float4*>(hist_out + (size_t)row * X_DIM)[tid] = o;
    }
}

extern "C" void kernel_launch(void* const* d_in, const int* in_sizes, int n_in,
                              void* d_out, int out_size)
{
    const int* duration      = (const int*)d_in[0];   // (B, Y) int32
    const int* output_length = (const int*)d_in[1];   // (B,)   int32
    // d_in[2] (x_steps) is the compile-time constant X_DIM = 1024.

    float* weights_out = (float*)d_out;                         // B*Y floats
    float* hist_out    = (float*)d_out + (size_t)B_DIM * Y_DIM; // B*X floats

    duration_calc_kernel<<<4 * B_DIM, 256>>>(duration, output_length,
                                             weights_out, hist_out);
}